// round 2
// baseline (speedup 1.0000x reference)
#include <cuda_runtime.h>

#define B_  2
#define T_  2048
#define DM_ 1024
#define H_  16
#define D_  64
#define M_  (B_*T_)   // 4096 rows

// Scratch (allocation-free rule: __device__ globals)
__device__ float g_q[B_*T_*DM_];
__device__ float g_k[B_*T_*DM_];
__device__ float g_v[B_*T_*DM_];
__device__ float g_a[B_*T_*DM_];

// ---------------------------------------------------------------------------
// C[M,1024] = A[M,1024] @ W[1024,1024]^T + bias, optional fused RoPE epilogue.
// 128x128 block tile, BK=8, 256 threads, 8x8 per-thread microtile.
// ---------------------------------------------------------------------------
__global__ __launch_bounds__(256) void gemm_xwt(
    const float* __restrict__ A, const float* __restrict__ W,
    const float* __restrict__ bias, float* __restrict__ C,
    const float* __restrict__ cs, const float* __restrict__ sn, int rope)
{
    __shared__ float As[8][136];
    __shared__ float Bs[8][136];
    const int tid = threadIdx.x;
    const int m0 = blockIdx.y * 128;
    const int n0 = blockIdx.x * 128;
    const int lr = tid >> 1;          // 0..127
    const int lk = (tid & 1) << 2;    // 0 or 4
    const float* Ag = A + (size_t)(m0 + lr) * DM_ + lk;
    const float* Wg = W + (size_t)(n0 + lr) * DM_ + lk;
    const int ty = tid >> 4;          // 0..15
    const int tx = tid & 15;          // 0..15

    float acc[8][8];
    #pragma unroll
    for (int i = 0; i < 8; i++)
        #pragma unroll
        for (int j = 0; j < 8; j++) acc[i][j] = 0.f;

    for (int k0 = 0; k0 < DM_; k0 += 8) {
        float4 av = *(const float4*)(Ag + k0);
        float4 wv = *(const float4*)(Wg + k0);
        As[lk+0][lr] = av.x; As[lk+1][lr] = av.y;
        As[lk+2][lr] = av.z; As[lk+3][lr] = av.w;
        Bs[lk+0][lr] = wv.x; Bs[lk+1][lr] = wv.y;
        Bs[lk+2][lr] = wv.z; Bs[lk+3][lr] = wv.w;
        __syncthreads();
        #pragma unroll
        for (int kk = 0; kk < 8; kk++) {
            float4 a0 = *(const float4*)&As[kk][ty*8];
            float4 a1 = *(const float4*)&As[kk][ty*8+4];
            float4 b0 = *(const float4*)&Bs[kk][tx*8];
            float4 b1 = *(const float4*)&Bs[kk][tx*8+4];
            float a[8] = {a0.x,a0.y,a0.z,a0.w,a1.x,a1.y,a1.z,a1.w};
            float b[8] = {b0.x,b0.y,b0.z,b0.w,b1.x,b1.y,b1.z,b1.w};
            #pragma unroll
            for (int i = 0; i < 8; i++)
                #pragma unroll
                for (int j = 0; j < 8; j++)
                    acc[i][j] = fmaf(a[i], b[j], acc[i][j]);
        }
        __syncthreads();
    }

    float bv_[8], c_[8], s_[8];
    #pragma unroll
    for (int j = 0; j < 8; j++) {
        int n = n0 + tx*8 + j;
        bv_[j] = bias[n];
        if (rope) { c_[j] = cs[n & 63]; s_[j] = sn[n & 63]; }
    }
    #pragma unroll
    for (int i = 0; i < 8; i++) {
        float out[8];
        #pragma unroll
        for (int j = 0; j < 8; j++) out[j] = acc[i][j] + bv_[j];
        if (rope) {
            // y[2i]   =  x[2i]*c - x[2i+1]*s
            // y[2i+1] =  x[2i]*s + x[2i+1]*c   (cos/sin repeated per pair)
            #pragma unroll
            for (int j = 0; j < 8; j += 2) {
                float x0 = out[j], x1 = out[j+1];
                out[j]   = x0 * c_[j]   - x1 * s_[j];
                out[j+1] = x0 * s_[j+1] + x1 * c_[j+1];
            }
        }
        float* Cp = C + (size_t)(m0 + ty*8 + i) * DM_ + n0 + tx*8;
        *(float4*)Cp     = make_float4(out[0],out[1],out[2],out[3]);
        *(float4*)(Cp+4) = make_float4(out[4],out[5],out[6],out[7]);
    }
}

// ---------------------------------------------------------------------------
// Flash attention, fp32. One block = 64 q-rows of one (b,h) pair.
// Per-(b,h) head matrices are contiguous [T,64] slabs (scrambled-view layout).
// Writes attention output in [b, t, h*64+d] layout (the transpose+reshape).
// ---------------------------------------------------------------------------
__global__ __launch_bounds__(256) void attn_fwd(
    const float* __restrict__ Qb, const float* __restrict__ Kb,
    const float* __restrict__ Vb, float* __restrict__ Ob)
{
    extern __shared__ float sm[];
    float* Qs = sm;                 // 64 x 64
    float* Kt = sm + 64*64;         // 64 x 68 (K transposed; reused as P)
    float* Vs = Kt + 64*68;         // 64 x 64

    const int tid = threadIdx.x;
    const int ty = tid >> 4, tx = tid & 15;
    const int q0 = blockIdx.x * 64;
    const int bh = blockIdx.y;
    const int bb = bh >> 4, hh = bh & 15;
    const size_t base = (size_t)bb * T_ * DM_ + (size_t)hh * T_ * D_;
    const float* Qh = Qb + base;
    const float* Kh = Kb + base;
    const float* Vh = Vb + base;

    const int lrow = tid >> 4;        // 0..15
    const int ld4  = (tid & 15) << 2; // 0..60

    // Load Q tile, pre-scaled by 1/sqrt(64)
    #pragma unroll
    for (int p = 0; p < 4; p++) {
        int r = p*16 + lrow;
        float4 v = *(const float4*)(Qh + (size_t)(q0 + r) * D_ + ld4);
        *(float4*)&Qs[r*64 + ld4] =
            make_float4(v.x*0.125f, v.y*0.125f, v.z*0.125f, v.w*0.125f);
    }

    float m_[4], l_[4], o_[4][4];
    #pragma unroll
    for (int i = 0; i < 4; i++) {
        m_[i] = -1e30f; l_[i] = 0.f;
        #pragma unroll
        for (int j = 0; j < 4; j++) o_[i][j] = 0.f;
    }

    for (int kt = 0; kt < T_/64; kt++) {
        __syncthreads();   // previous PV done (and Q visible on iter 0)
        #pragma unroll
        for (int p = 0; p < 4; p++) {
            int j = p*16 + lrow;
            float4 kv = *(const float4*)(Kh + (size_t)(kt*64 + j) * D_ + ld4);
            Kt[(ld4+0)*68 + j] = kv.x;
            Kt[(ld4+1)*68 + j] = kv.y;
            Kt[(ld4+2)*68 + j] = kv.z;
            Kt[(ld4+3)*68 + j] = kv.w;
            float4 vv = *(const float4*)(Vh + (size_t)(kt*64 + j) * D_ + ld4);
            *(float4*)&Vs[j*64 + ld4] = vv;
        }
        __syncthreads();

        // S = (Q/8) K^T   (4x4 per thread: rows ty*4+ii, cols tx*4+jj)
        float s_[4][4];
        #pragma unroll
        for (int i = 0; i < 4; i++)
            #pragma unroll
            for (int j = 0; j < 4; j++) s_[i][j] = 0.f;
        #pragma unroll 16
        for (int d = 0; d < 64; d++) {
            float4 kb = *(const float4*)&Kt[d*68 + tx*4];
            float q0v = Qs[(ty*4+0)*64 + d];
            float q1v = Qs[(ty*4+1)*64 + d];
            float q2v = Qs[(ty*4+2)*64 + d];
            float q3v = Qs[(ty*4+3)*64 + d];
            s_[0][0]=fmaf(q0v,kb.x,s_[0][0]); s_[0][1]=fmaf(q0v,kb.y,s_[0][1]);
            s_[0][2]=fmaf(q0v,kb.z,s_[0][2]); s_[0][3]=fmaf(q0v,kb.w,s_[0][3]);
            s_[1][0]=fmaf(q1v,kb.x,s_[1][0]); s_[1][1]=fmaf(q1v,kb.y,s_[1][1]);
            s_[1][2]=fmaf(q1v,kb.z,s_[1][2]); s_[1][3]=fmaf(q1v,kb.w,s_[1][3]);
            s_[2][0]=fmaf(q2v,kb.x,s_[2][0]); s_[2][1]=fmaf(q2v,kb.y,s_[2][1]);
            s_[2][2]=fmaf(q2v,kb.z,s_[2][2]); s_[2][3]=fmaf(q2v,kb.w,s_[2][3]);
            s_[3][0]=fmaf(q3v,kb.x,s_[3][0]); s_[3][1]=fmaf(q3v,kb.y,s_[3][1]);
            s_[3][2]=fmaf(q3v,kb.z,s_[3][2]); s_[3][3]=fmaf(q3v,kb.w,s_[3][3]);
        }

        // Online softmax (row groups = 16 lanes sharing ty; xor 1,2,4,8 stays in-group)
        float mt[4], rs[4];
        #pragma unroll
        for (int i = 0; i < 4; i++)
            mt[i] = fmaxf(fmaxf(s_[i][0], s_[i][1]), fmaxf(s_[i][2], s_[i][3]));
        #pragma unroll
        for (int off = 1; off <= 8; off <<= 1)
            #pragma unroll
            for (int i = 0; i < 4; i++)
                mt[i] = fmaxf(mt[i], __shfl_xor_sync(0xffffffffu, mt[i], off));
        float esc[4];
        #pragma unroll
        for (int i = 0; i < 4; i++) {
            float mn = fmaxf(m_[i], mt[i]);
            esc[i] = __expf(m_[i] - mn);
            m_[i] = mn;
        }
        #pragma unroll
        for (int i = 0; i < 4; i++) {
            float r = 0.f;
            #pragma unroll
            for (int j = 0; j < 4; j++) {
                s_[i][j] = __expf(s_[i][j] - m_[i]);
                r += s_[i][j];
            }
            rs[i] = r;
        }
        #pragma unroll
        for (int off = 1; off <= 8; off <<= 1)
            #pragma unroll
            for (int i = 0; i < 4; i++)
                rs[i] += __shfl_xor_sync(0xffffffffu, rs[i], off);
        #pragma unroll
        for (int i = 0; i < 4; i++) {
            l_[i] = l_[i] * esc[i] + rs[i];
            #pragma unroll
            for (int j = 0; j < 4; j++) o_[i][j] *= esc[i];
        }

        __syncthreads();   // everyone done reading Kt as K
        #pragma unroll
        for (int i = 0; i < 4; i++)
            *(float4*)&Kt[(ty*4+i)*68 + tx*4] =
                make_float4(s_[i][0], s_[i][1], s_[i][2], s_[i][3]);
        __syncthreads();

        // O += P V
        #pragma unroll 16
        for (int j = 0; j < 64; j++) {
            float4 vv = *(const float4*)&Vs[j*64 + tx*4];
            float p0v = Kt[(ty*4+0)*68 + j];
            float p1v = Kt[(ty*4+1)*68 + j];
            float p2v = Kt[(ty*4+2)*68 + j];
            float p3v = Kt[(ty*4+3)*68 + j];
            o_[0][0]=fmaf(p0v,vv.x,o_[0][0]); o_[0][1]=fmaf(p0v,vv.y,o_[0][1]);
            o_[0][2]=fmaf(p0v,vv.z,o_[0][2]); o_[0][3]=fmaf(p0v,vv.w,o_[0][3]);
            o_[1][0]=fmaf(p1v,vv.x,o_[1][0]); o_[1][1]=fmaf(p1v,vv.y,o_[1][1]);
            o_[1][2]=fmaf(p1v,vv.z,o_[1][2]); o_[1][3]=fmaf(p1v,vv.w,o_[1][3]);
            o_[2][0]=fmaf(p2v,vv.x,o_[2][0]); o_[2][1]=fmaf(p2v,vv.y,o_[2][1]);
            o_[2][2]=fmaf(p2v,vv.z,o_[2][2]); o_[2][3]=fmaf(p2v,vv.w,o_[2][3]);
            o_[3][0]=fmaf(p3v,vv.x,o_[3][0]); o_[3][1]=fmaf(p3v,vv.y,o_[3][1]);
            o_[3][2]=fmaf(p3v,vv.z,o_[3][2]); o_[3][3]=fmaf(p3v,vv.w,o_[3][3]);
        }
    }

    // Normalize, write in (b, t, h*64+d) layout
    #pragma unroll
    for (int i = 0; i < 4; i++) {
        float inv = 1.f / l_[i];
        float* Op = Ob + (size_t)bb * T_ * DM_
                       + (size_t)(q0 + ty*4 + i) * DM_ + hh*D_ + tx*4;
        *(float4*)Op = make_float4(o_[i][0]*inv, o_[i][1]*inv,
                                   o_[i][2]*inv, o_[i][3]*inv);
    }
}

// ---------------------------------------------------------------------------
extern "C" void kernel_launch(void* const* d_in, const int* in_sizes, int n_in,
                              void* d_out, int out_size)
{
    const float* x    = (const float*)d_in[0];
    const float* wq   = (const float*)d_in[1];
    const float* bq   = (const float*)d_in[2];
    const float* wk   = (const float*)d_in[3];
    const float* bk   = (const float*)d_in[4];
    const float* wv   = (const float*)d_in[5];
    const float* bv   = (const float*)d_in[6];
    const float* wo   = (const float*)d_in[7];
    const float* bo   = (const float*)d_in[8];
    const float* cosb = (const float*)d_in[9];
    const float* sinb = (const float*)d_in[10];
    float* out = (float*)d_out;

    float *qp, *kp, *vp, *ap;
    cudaGetSymbolAddress((void**)&qp, g_q);
    cudaGetSymbolAddress((void**)&kp, g_k);
    cudaGetSymbolAddress((void**)&vp, g_v);
    cudaGetSymbolAddress((void**)&ap, g_a);

    // Reference indexes cos/sin at the single row t = T (broadcast over positions)
    const float* cs = cosb + (size_t)T_ * D_;
    const float* sn = sinb + (size_t)T_ * D_;

    dim3 gg(DM_/128, M_/128);  // 8 x 32
    gemm_xwt<<<gg, 256>>>(x, wq, bq, qp, cs, sn, 1);
    gemm_xwt<<<gg, 256>>>(x, wk, bk, kp, cs, sn, 1);
    gemm_xwt<<<gg, 256>>>(x, wv, bv, vp, cs, sn, 0);

    const int attn_smem = (64*64 + 64*68 + 64*64) * 4;  // 50176 B
    cudaFuncSetAttribute(attn_fwd, cudaFuncAttributeMaxDynamicSharedMemorySize,
                         attn_smem);
    attn_fwd<<<dim3(T_/64, B_*H_), 256, attn_smem>>>(qp, kp, vp, ap);

    gemm_xwt<<<gg, 256>>>(ap, wo, bo, out, cs, sn, 0);
}

// round 4
// speedup vs baseline: 2.1625x; 2.1625x over previous
#include <cuda_runtime.h>
#include <cstdint>

#define B_  2
#define T_  2048
#define DM_ 1024
#define H_  16
#define D_  64
#define M_  (B_*T_)   // 4096 rows

// Scratch (allocation-free rule: __device__ globals)
__device__ float g_q[B_*T_*DM_];
__device__ float g_k[B_*T_*DM_];
__device__ float g_v[B_*T_*DM_];
__device__ float g_a[B_*T_*DM_];

__device__ __forceinline__ uint32_t f2tf(float x) {
    uint32_t r;
    asm("cvt.rna.tf32.f32 %0, %1;" : "=r"(r) : "f"(x));
    return r;
}

__device__ __forceinline__ void mma_tf32(
    float& d0, float& d1, float& d2, float& d3,
    uint32_t a0, uint32_t a1, uint32_t a2, uint32_t a3,
    uint32_t b0, uint32_t b1)
{
    asm volatile(
        "mma.sync.aligned.m16n8k8.row.col.f32.tf32.tf32.f32 "
        "{%0,%1,%2,%3}, {%4,%5,%6,%7}, {%8,%9}, {%0,%1,%2,%3};"
        : "+f"(d0), "+f"(d1), "+f"(d2), "+f"(d3)
        : "r"(a0), "r"(a1), "r"(a2), "r"(a3), "r"(b0), "r"(b1));
}

// ---------------------------------------------------------------------------
// C[M,1024] = A[M,1024] @ W[1024,1024]^T + bias (+ fused RoPE), tf32 mma.
// Block tile 128x128, BK=16, 256 threads = 8 warps (4x2), warp tile 32x64.
// smem row stride 20 words -> conflict-free fragment loads.
// ---------------------------------------------------------------------------
__global__ __launch_bounds__(256) void gemm_tf32(
    const float* __restrict__ A, const float* __restrict__ W,
    const float* __restrict__ bias, float* __restrict__ C,
    const float* __restrict__ cs, const float* __restrict__ sn, int rope)
{
    __shared__ uint32_t As[128][20];
    __shared__ uint32_t Ws[128][20];

    const int tid  = threadIdx.x;
    const int lane = tid & 31;
    const int wid  = tid >> 5;
    const int m0 = blockIdx.y * 128;
    const int n0 = blockIdx.x * 128;
    const int wm = (wid >> 1) * 32;   // warp row offset
    const int wn = (wid & 1) * 64;    // warp col offset
    const int qg = lane >> 2;         // groupID 0..7
    const int qt = lane & 3;          // thread-in-group 0..3

    const int lr = tid >> 1;          // 0..127 (load row)
    const int lq = (tid & 1) * 8;     // 0 or 8 (load k base)

    const float* Ag = A + (size_t)(m0 + lr) * DM_ + lq;
    const float* Wg = W + (size_t)(n0 + lr) * DM_ + lq;

    float acc[2][8][4];
    #pragma unroll
    for (int mt = 0; mt < 2; mt++)
        #pragma unroll
        for (int nt = 0; nt < 8; nt++)
            #pragma unroll
            for (int c = 0; c < 4; c++) acc[mt][nt][c] = 0.f;

    float4 pa0 = *(const float4*)(Ag);
    float4 pa1 = *(const float4*)(Ag + 4);
    float4 pw0 = *(const float4*)(Wg);
    float4 pw1 = *(const float4*)(Wg + 4);

    for (int k0 = 0; k0 < DM_; k0 += 16) {
        // store current prefetch into smem (tf32-converted)
        {
            float va[8] = {pa0.x,pa0.y,pa0.z,pa0.w,pa1.x,pa1.y,pa1.z,pa1.w};
            float vw[8] = {pw0.x,pw0.y,pw0.z,pw0.w,pw1.x,pw1.y,pw1.z,pw1.w};
            #pragma unroll
            for (int i = 0; i < 8; i++) {
                As[lr][lq + i] = f2tf(va[i]);
                Ws[lr][lq + i] = f2tf(vw[i]);
            }
        }
        __syncthreads();

        if (k0 + 16 < DM_) {
            pa0 = *(const float4*)(Ag + k0 + 16);
            pa1 = *(const float4*)(Ag + k0 + 20);
            pw0 = *(const float4*)(Wg + k0 + 16);
            pw1 = *(const float4*)(Wg + k0 + 20);
        }

        #pragma unroll
        for (int ks = 0; ks < 2; ks++) {
            const int kk = ks * 8;
            uint32_t af[2][4];
            #pragma unroll
            for (int mt = 0; mt < 2; mt++) {
                int r = wm + mt*16 + qg;
                af[mt][0] = As[r    ][kk + qt];
                af[mt][1] = As[r + 8][kk + qt];
                af[mt][2] = As[r    ][kk + qt + 4];
                af[mt][3] = As[r + 8][kk + qt + 4];
            }
            #pragma unroll
            for (int nt = 0; nt < 8; nt++) {
                int n = wn + nt*8 + qg;
                uint32_t b0 = Ws[n][kk + qt];
                uint32_t b1 = Ws[n][kk + qt + 4];
                #pragma unroll
                for (int mt = 0; mt < 2; mt++)
                    mma_tf32(acc[mt][nt][0], acc[mt][nt][1],
                             acc[mt][nt][2], acc[mt][nt][3],
                             af[mt][0], af[mt][1], af[mt][2], af[mt][3],
                             b0, b1);
            }
        }
        __syncthreads();
    }

    // Epilogue: bias + optional RoPE (C-frag holds adjacent col pairs)
    #pragma unroll
    for (int nt = 0; nt < 8; nt++) {
        const int n = n0 + wn + nt*8 + 2*qt;
        const float bv0 = bias[n], bv1 = bias[n+1];
        float cr = 1.f, sr = 0.f;
        if (rope) { cr = cs[n & 63]; sr = sn[n & 63]; }
        #pragma unroll
        for (int mt = 0; mt < 2; mt++) {
            float x0 = acc[mt][nt][0] + bv0;
            float x1 = acc[mt][nt][1] + bv1;
            float y0 = acc[mt][nt][2] + bv0;
            float y1 = acc[mt][nt][3] + bv1;
            if (rope) {
                float t0 = x0*cr - x1*sr, t1 = x0*sr + x1*cr;
                x0 = t0; x1 = t1;
                t0 = y0*cr - y1*sr; t1 = y0*sr + y1*cr;
                y0 = t0; y1 = t1;
            }
            const int r = m0 + wm + mt*16 + qg;
            *(float2*)(C + (size_t)r * DM_ + n)       = make_float2(x0, x1);
            *(float2*)(C + (size_t)(r+8) * DM_ + n)   = make_float2(y0, y1);
        }
    }
}

// ---------------------------------------------------------------------------
// Flash attention, tf32 mma. Block = 128 q-rows of one (b,h); 64-key tiles.
// 8 warps, each owns 16 q-rows (all 64 key/dim cols).
// smem: Qs[128][68] Ks[64][68] Vs[64][72] Ps[128][68] (tf32 bits), 105472 B.
// ---------------------------------------------------------------------------
__global__ __launch_bounds__(256) void attn_tf32(
    const float* __restrict__ Qb, const float* __restrict__ Kb,
    const float* __restrict__ Vb, float* __restrict__ Ob)
{
    extern __shared__ uint32_t sm[];
    uint32_t* Qs = sm;                  // [128][68]
    uint32_t* Ks = Qs + 128*68;         // [64][68]
    uint32_t* Vs = Ks + 64*68;          // [64][72]
    uint32_t* Ps = Vs + 64*72;          // [128][68]

    const int tid  = threadIdx.x;
    const int lane = tid & 31;
    const int wid  = tid >> 5;
    const int wm   = wid * 16;          // warp's q-row base (local)
    const int qg = lane >> 2;           // 0..7
    const int qt = lane & 3;            // 0..3

    const int q0 = blockIdx.x * 128;
    const int bh = blockIdx.y;
    const int bb = bh >> 4, hh = bh & 15;
    const size_t base = (size_t)bb * T_ * DM_ + (size_t)hh * T_ * D_;
    const float* Qh = Qb + base;
    const float* Kh = Kb + base;
    const float* Vh = Vb + base;

    // Load Q tile (prescaled by 1/8, tf32)
    {
        const int r = tid >> 1;
        const int c0 = (tid & 1) * 32;
        #pragma unroll
        for (int p = 0; p < 8; p++) {
            float4 v = *(const float4*)(Qh + (size_t)(q0 + r) * D_ + c0 + p*4);
            Qs[r*68 + c0 + p*4 + 0] = f2tf(v.x * 0.125f);
            Qs[r*68 + c0 + p*4 + 1] = f2tf(v.y * 0.125f);
            Qs[r*68 + c0 + p*4 + 2] = f2tf(v.z * 0.125f);
            Qs[r*68 + c0 + p*4 + 3] = f2tf(v.w * 0.125f);
        }
    }

    float oacc[8][4];
    #pragma unroll
    for (int nt = 0; nt < 8; nt++)
        #pragma unroll
        for (int c = 0; c < 4; c++) oacc[nt][c] = 0.f;
    float rm0 = -1e30f, rm1 = -1e30f, rl0 = 0.f, rl1 = 0.f;

    for (int kt = 0; kt < T_/64; kt++) {
        __syncthreads();   // prev PV done reading Vs/Ps; Q visible on iter 0
        // Fill K (tf32) and V (tf32) tiles
        {
            const int r = tid >> 2;            // 0..63
            const int c0 = (tid & 3) * 16;
            #pragma unroll
            for (int p = 0; p < 4; p++) {
                float4 kv = *(const float4*)(Kh + (size_t)(kt*64 + r) * D_ + c0 + p*4);
                Ks[r*68 + c0 + p*4 + 0] = f2tf(kv.x);
                Ks[r*68 + c0 + p*4 + 1] = f2tf(kv.y);
                Ks[r*68 + c0 + p*4 + 2] = f2tf(kv.z);
                Ks[r*68 + c0 + p*4 + 3] = f2tf(kv.w);
                float4 vv = *(const float4*)(Vh + (size_t)(kt*64 + r) * D_ + c0 + p*4);
                Vs[r*72 + c0 + p*4 + 0] = f2tf(vv.x);
                Vs[r*72 + c0 + p*4 + 1] = f2tf(vv.y);
                Vs[r*72 + c0 + p*4 + 2] = f2tf(vv.z);
                Vs[r*72 + c0 + p*4 + 3] = f2tf(vv.w);
            }
        }
        __syncthreads();

        // S = (Q/8) K^T : 8 ksteps x 8 ntiles
        float sacc[8][4];
        #pragma unroll
        for (int nt = 0; nt < 8; nt++)
            #pragma unroll
            for (int c = 0; c < 4; c++) sacc[nt][c] = 0.f;
        #pragma unroll
        for (int ks = 0; ks < 8; ks++) {
            const int kk = ks * 8;
            const int r = wm + qg;
            uint32_t a0 = Qs[r*68      + kk + qt];
            uint32_t a1 = Qs[(r+8)*68  + kk + qt];
            uint32_t a2 = Qs[r*68      + kk + qt + 4];
            uint32_t a3 = Qs[(r+8)*68  + kk + qt + 4];
            #pragma unroll
            for (int nt = 0; nt < 8; nt++) {
                const int n = nt*8 + qg;
                uint32_t b0 = Ks[n*68 + kk + qt];
                uint32_t b1 = Ks[n*68 + kk + qt + 4];
                mma_tf32(sacc[nt][0], sacc[nt][1], sacc[nt][2], sacc[nt][3],
                         a0, a1, a2, a3, b0, b1);
            }
        }

        // Online softmax. Thread owns rows r0=wm+qg, r1=r0+8; 16 cols each.
        float mt0 = -1e30f, mt1 = -1e30f;
        #pragma unroll
        for (int nt = 0; nt < 8; nt++) {
            mt0 = fmaxf(mt0, fmaxf(sacc[nt][0], sacc[nt][1]));
            mt1 = fmaxf(mt1, fmaxf(sacc[nt][2], sacc[nt][3]));
        }
        #pragma unroll
        for (int off = 1; off <= 2; off <<= 1) {
            mt0 = fmaxf(mt0, __shfl_xor_sync(0xffffffffu, mt0, off));
            mt1 = fmaxf(mt1, __shfl_xor_sync(0xffffffffu, mt1, off));
        }
        const float mn0 = fmaxf(rm0, mt0), mn1 = fmaxf(rm1, mt1);
        const float esc0 = __expf(rm0 - mn0), esc1 = __expf(rm1 - mn1);
        rm0 = mn0; rm1 = mn1;

        float rs0 = 0.f, rs1 = 0.f;
        #pragma unroll
        for (int nt = 0; nt < 8; nt++) {
            sacc[nt][0] = __expf(sacc[nt][0] - mn0);
            sacc[nt][1] = __expf(sacc[nt][1] - mn0);
            sacc[nt][2] = __expf(sacc[nt][2] - mn1);
            sacc[nt][3] = __expf(sacc[nt][3] - mn1);
            rs0 += sacc[nt][0] + sacc[nt][1];
            rs1 += sacc[nt][2] + sacc[nt][3];
        }
        #pragma unroll
        for (int off = 1; off <= 2; off <<= 1) {
            rs0 += __shfl_xor_sync(0xffffffffu, rs0, off);
            rs1 += __shfl_xor_sync(0xffffffffu, rs1, off);
        }
        rl0 = rl0 * esc0 + rs0;
        rl1 = rl1 * esc1 + rs1;
        #pragma unroll
        for (int nt = 0; nt < 8; nt++) {
            oacc[nt][0] *= esc0; oacc[nt][1] *= esc0;
            oacc[nt][2] *= esc1; oacc[nt][3] *= esc1;
        }

        // Stage P (tf32) — each warp writes & reads only its own 16 rows
        {
            const int r0 = wm + qg, r1 = r0 + 8;
            #pragma unroll
            for (int nt = 0; nt < 8; nt++) {
                const int c = nt*8 + 2*qt;
                Ps[r0*68 + c]     = f2tf(sacc[nt][0]);
                Ps[r0*68 + c + 1] = f2tf(sacc[nt][1]);
                Ps[r1*68 + c]     = f2tf(sacc[nt][2]);
                Ps[r1*68 + c + 1] = f2tf(sacc[nt][3]);
            }
        }
        __syncwarp();

        // O += P V : 8 ksteps (keys) x 8 ntiles (dims)
        #pragma unroll
        for (int ks = 0; ks < 8; ks++) {
            const int kk = ks * 8;
            const int r = wm + qg;
            uint32_t a0 = Ps[r*68      + kk + qt];
            uint32_t a1 = Ps[(r+8)*68  + kk + qt];
            uint32_t a2 = Ps[r*68      + kk + qt + 4];
            uint32_t a3 = Ps[(r+8)*68  + kk + qt + 4];
            #pragma unroll
            for (int nt = 0; nt < 8; nt++) {
                uint32_t b0 = Vs[(kk + qt)*72     + nt*8 + qg];
                uint32_t b1 = Vs[(kk + qt + 4)*72 + nt*8 + qg];
                mma_tf32(oacc[nt][0], oacc[nt][1], oacc[nt][2], oacc[nt][3],
                         a0, a1, a2, a3, b0, b1);
            }
        }
    }

    // Normalize + write, (b, t, h*64+dim) layout
    const float inv0 = 1.f / rl0, inv1 = 1.f / rl1;
    const int r0g = q0 + wm + qg, r1g = r0g + 8;
    float* O0 = Ob + (size_t)bb * T_ * DM_ + (size_t)r0g * DM_ + hh*D_;
    float* O1 = Ob + (size_t)bb * T_ * DM_ + (size_t)r1g * DM_ + hh*D_;
    #pragma unroll
    for (int nt = 0; nt < 8; nt++) {
        const int c = nt*8 + 2*qt;
        *(float2*)(O0 + c) = make_float2(oacc[nt][0]*inv0, oacc[nt][1]*inv0);
        *(float2*)(O1 + c) = make_float2(oacc[nt][2]*inv1, oacc[nt][3]*inv1);
    }
}

// ---------------------------------------------------------------------------
extern "C" void kernel_launch(void* const* d_in, const int* in_sizes, int n_in,
                              void* d_out, int out_size)
{
    const float* x    = (const float*)d_in[0];
    const float* wq   = (const float*)d_in[1];
    const float* bq   = (const float*)d_in[2];
    const float* wk   = (const float*)d_in[3];
    const float* bk   = (const float*)d_in[4];
    const float* wv   = (const float*)d_in[5];
    const float* bv   = (const float*)d_in[6];
    const float* wo   = (const float*)d_in[7];
    const float* bo   = (const float*)d_in[8];
    const float* cosb = (const float*)d_in[9];
    const float* sinb = (const float*)d_in[10];
    float* out = (float*)d_out;

    float *qp, *kp, *vp, *ap;
    cudaGetSymbolAddress((void**)&qp, g_q);
    cudaGetSymbolAddress((void**)&kp, g_k);
    cudaGetSymbolAddress((void**)&vp, g_v);
    cudaGetSymbolAddress((void**)&ap, g_a);

    // Reference indexes cos/sin at the single row t = T (broadcast)
    const float* cs = cosb + (size_t)T_ * D_;
    const float* sn = sinb + (size_t)T_ * D_;

    dim3 gg(DM_/128, M_/128);  // 8 x 32
    gemm_tf32<<<gg, 256>>>(x, wq, bq, qp, cs, sn, 1);
    gemm_tf32<<<gg, 256>>>(x, wk, bk, kp, cs, sn, 1);
    gemm_tf32<<<gg, 256>>>(x, wv, bv, vp, cs, sn, 0);

    const int attn_smem = (128*68 + 64*68 + 64*72 + 128*68) * 4;  // 105472
    static int attn_cfg = 0;
    if (!attn_cfg) {
        cudaFuncSetAttribute(attn_tf32,
            cudaFuncAttributeMaxDynamicSharedMemorySize, attn_smem);
        attn_cfg = 1;
    }
    attn_tf32<<<dim3(T_/128, B_*H_), 256, attn_smem>>>(qp, kp, vp, ap);

    gemm_tf32<<<gg, 256>>>(ap, wo, bo, out, cs, sn, 0);
}